// round 12
// baseline (speedup 1.0000x reference)
#include <cuda_runtime.h>
#include <cuda_bf16.h>
#include <cstdint>

typedef unsigned long long u64;

// Problem dims
#define TT 2048
#define BB 16
#define II 512
#define HH 512
#define BH (BB*HH)   // 8192
#define RR (TT/8)    // 256 scan rounds (8-step blocking)

#define CLUSTER 8    // CTAs per cluster = 1 batch per cluster, 64 cols per CTA

// Scratch: W^2, W^4, W^8, row-major [512][512]. Static __device__ (legal).
__device__ float g_W2[HH * HH];
__device__ float g_W4[HH * HH];
__device__ float g_W8[HH * HH];

static __device__ __forceinline__ uint32_t smem_u32(const void* p) {
    uint32_t a;
    asm("{ .reg .u64 t; cvta.to.shared.u64 t, %1; cvt.u32.u64 %0, t; }"
        : "=r"(a) : "l"(p));
    return a;
}

#define FMA2(acc, a, b) \
    asm("fma.rn.f32x2 %0, %1, %2, %0;" : "+l"(acc) : "l"(a), "l"(b))
#define SPLAT2(dst, f) \
    asm("mov.b64 %0, {%1, %1};" : "=l"(dst) : "r"(__float_as_uint(f)))

// ---------------------------------------------------------------------------
// Kernel 1: x_proj. 128x128 tile, 256 threads, 8x8 microtile (f32x2 m-pairs).
// Conflict-free transpose store: loader lanes span rows for fixed k.
// ---------------------------------------------------------------------------
__global__ __launch_bounds__(256)
void xproj_kernel(const float* __restrict__ A,      // inputs [M][512]
                  const float* __restrict__ W,      // weight [512][1024]
                  const float* __restrict__ bias,   // [512]
                  float* __restrict__ out)          // [M][512]
{
    __shared__ float As[32][132];   // [k][m]
    __shared__ float Bs[32][132];   // [k][n]

    const int tid = threadIdx.x;
    const int bm = blockIdx.x * 128;
    const int bn = blockIdx.y * 128;
    const int tx = tid & 15;    // n: 8 cols at bn + tx*8
    const int ty = tid >> 4;    // m: 8 rows at bm + ty*8

    u64 acc2[4][8];
#pragma unroll
    for (int r = 0; r < 4; r++)
#pragma unroll
        for (int c = 0; c < 8; c++) acc2[r][c] = 0ull;

#pragma unroll 1
    for (int kt = 0; kt < 16; kt++) {
        const int k0 = kt * 32;
        // A: 128 rows x 32 k -> 1024 float4, 4/thread; lanes span rows.
#pragma unroll
        for (int j = 0; j < 4; j++) {
            int idx = tid + j * 256;
            int row = idx & 127;
            int kq  = idx >> 7;      // 0..7
            float4 v = *reinterpret_cast<const float4*>(
                &A[(size_t)(bm + row) * 512 + k0 + kq * 4]);
            As[kq * 4 + 0][row] = v.x;
            As[kq * 4 + 1][row] = v.y;
            As[kq * 4 + 2][row] = v.z;
            As[kq * 4 + 3][row] = v.w;
        }
        // B: w_xh rows (cols [512,1024) of weight)
#pragma unroll
        for (int j = 0; j < 4; j++) {
            int idx = tid + j * 256;
            int col = idx & 127;
            int kq  = idx >> 7;
            float4 v = *reinterpret_cast<const float4*>(
                &W[(size_t)(bn + col) * 1024 + 512 + k0 + kq * 4]);
            Bs[kq * 4 + 0][col] = v.x;
            Bs[kq * 4 + 1][col] = v.y;
            Bs[kq * 4 + 2][col] = v.z;
            Bs[kq * 4 + 3][col] = v.w;
        }
        __syncthreads();

#pragma unroll
        for (int k = 0; k < 32; k++) {
            const ulonglong2* ap = reinterpret_cast<const ulonglong2*>(&As[k][ty * 8]);
            ulonglong2 a01 = ap[0];
            ulonglong2 a23 = ap[1];
            float4 b0 = *reinterpret_cast<const float4*>(&Bs[k][tx * 8]);
            float4 b1 = *reinterpret_cast<const float4*>(&Bs[k][tx * 8 + 4]);
            u64 bs[8];
            SPLAT2(bs[0], b0.x); SPLAT2(bs[1], b0.y);
            SPLAT2(bs[2], b0.z); SPLAT2(bs[3], b0.w);
            SPLAT2(bs[4], b1.x); SPLAT2(bs[5], b1.y);
            SPLAT2(bs[6], b1.z); SPLAT2(bs[7], b1.w);
            u64 apair[4] = {a01.x, a01.y, a23.x, a23.y};
#pragma unroll
            for (int r = 0; r < 4; r++)
#pragma unroll
                for (int c = 0; c < 8; c++)
                    FMA2(acc2[r][c], apair[r], bs[c]);
        }
        __syncthreads();
    }

#pragma unroll
    for (int r = 0; r < 4; r++) {
        size_t row0 = (size_t)(bm + ty * 8 + 2 * r) * 512 + bn + tx * 8;
#pragma unroll
        for (int c = 0; c < 8; c++) {
            uint32_t lo, hi;
            asm("mov.b64 {%0, %1}, %2;" : "=r"(lo), "=r"(hi) : "l"(acc2[r][c]));
            float bv = bias[bn + tx * 8 + c];
            out[row0 + c]       = __uint_as_float(lo) + bv;
            out[row0 + 512 + c] = __uint_as_float(hi) + bv;
        }
    }
}

// ---------------------------------------------------------------------------
// Kernel 1b: matrix squaring: dst = src @ src (src rows stride sstride,
// w_hh submatrix = cols [0,512)). 64x64 tiles. ~10-15us each.
// ---------------------------------------------------------------------------
__global__ __launch_bounds__(256)
void mat_sq_kernel(const float* __restrict__ src, int sstride,
                   float* __restrict__ dst)
{
    __shared__ float As[32][68];   // [j][i]
    __shared__ float Bs[32][68];   // [j][k]

    const int tid = threadIdx.x;
    const int i0 = blockIdx.x * 64;
    const int k0g = blockIdx.y * 64;

    const int tx = tid & 15;
    const int ty = tid >> 4;

    float acc[4][4];
#pragma unroll
    for (int a = 0; a < 4; a++)
#pragma unroll
        for (int b = 0; b < 4; b++) acc[a][b] = 0.f;

#pragma unroll 1
    for (int jt = 0; jt < 16; jt++) {
        const int j0 = jt * 32;
#pragma unroll
        for (int l = 0; l < 2; l++) {
            int idx = tid + l * 256;
            int row = idx & 63;
            int q   = idx >> 6;     // 0..7
            float4 v = *reinterpret_cast<const float4*>(
                src + (size_t)(i0 + row) * sstride + j0 + q * 4);
            As[q * 4 + 0][row] = v.x;
            As[q * 4 + 1][row] = v.y;
            As[q * 4 + 2][row] = v.z;
            As[q * 4 + 3][row] = v.w;
        }
#pragma unroll
        for (int l = 0; l < 2; l++) {
            int idx = tid + l * 256;
            int col = idx & 63;
            int q   = idx >> 6;
            float4 v = *reinterpret_cast<const float4*>(
                src + (size_t)(j0 + ((q & 3) * 8) + (idx >> 8) * 0) * sstride + 0);
            // (unused dummy to keep structure simple)
            (void)v;
            // B tile: Bs[j][k] = src[j0+j][k0g+k]; lanes span cols for fixed j.
            float4 w = *reinterpret_cast<const float4*>(
                src + (size_t)(j0 + (idx >> 4 & 31) * 0 + 0) * 0 + 0);
            (void)w;
            break;
        }
        // B tile proper: 32 j-rows x 64 k = 512 float4, 2/thread
#pragma unroll
        for (int l = 0; l < 2; l++) {
            int idx = tid + l * 256;
            int jr  = idx >> 4;      // 0..31
            int q   = idx & 15;      // 0..15
            float4 v = *reinterpret_cast<const float4*>(
                src + (size_t)(j0 + jr) * sstride + k0g + q * 4);
            Bs[jr][q * 4 + 0] = v.x;
            Bs[jr][q * 4 + 1] = v.y;
            Bs[jr][q * 4 + 2] = v.z;
            Bs[jr][q * 4 + 3] = v.w;
        }
        __syncthreads();

#pragma unroll
        for (int j = 0; j < 32; j++) {
            float a[4], b[4];
#pragma unroll
            for (int x = 0; x < 4; x++) a[x] = As[j][ty * 4 + x];
#pragma unroll
            for (int x = 0; x < 4; x++) b[x] = Bs[j][tx * 4 + x];
#pragma unroll
            for (int x = 0; x < 4; x++)
#pragma unroll
                for (int y = 0; y < 4; y++)
                    acc[x][y] = fmaf(a[x], b[y], acc[x][y]);
        }
        __syncthreads();
    }

#pragma unroll
    for (int x = 0; x < 4; x++)
#pragma unroll
        for (int y = 0; y < 4; y++)
            dst[(size_t)(i0 + ty * 4 + x) * 512 + k0g + tx * 4 + y] = acc[x][y];
}

// ---------------------------------------------------------------------------
// Kernel 2: recurrent-side parallel GEMMs, 128x128 tile, 8x8 microtile.
// Row m -> (rr = m>>4, bb = m&15). Level stride s in {2,4,8}:
//  pre  (mode 0): D slot = s*rr + s-1 ; A slot = s*rr + s/2-1
//  post (mode 1): D slot = s*rr + s/2-1 ; A = (rr==0 ? state : slot s*rr-1)
// Wp rows stride wstride (1024 for weight/w_hh, 512 for g_W2/g_W4).
// ---------------------------------------------------------------------------
__global__ __launch_bounds__(256)
void rec_gemm_kernel(const float* __restrict__ Wp, int wstride,
                     const float* __restrict__ state,  // [16][512]
                     float* __restrict__ out,
                     int mode, int s)
{
    __shared__ float As[32][132];
    __shared__ float Bs[32][132];

    const int tid = threadIdx.x;
    const int bm = blockIdx.x * 128;
    const int bn = blockIdx.y * 128;
    const int tx = tid & 15;
    const int ty = tid >> 4;

    u64 acc2[4][8];
#pragma unroll
    for (int r = 0; r < 4; r++)
#pragma unroll
        for (int c = 0; c < 8; c++) acc2[r][c] = 0ull;

#pragma unroll 1
    for (int kt = 0; kt < 16; kt++) {
        const int k0 = kt * 32;
#pragma unroll
        for (int j = 0; j < 4; j++) {
            int idx = tid + j * 256;
            int row = idx & 127;
            int kq  = idx >> 7;
            int m   = bm + row;
            int rr  = m >> 4;
            int bb  = m & 15;
            const float* arow;
            if (mode == 0) {
                arow = out + (size_t)(s * rr + s / 2 - 1) * BH + (size_t)bb * 512;
            } else {
                arow = (rr == 0) ? (state + (size_t)bb * 512)
                                 : (out + (size_t)(s * rr - 1) * BH + (size_t)bb * 512);
            }
            float4 v = *reinterpret_cast<const float4*>(arow + k0 + kq * 4);
            As[kq * 4 + 0][row] = v.x;
            As[kq * 4 + 1][row] = v.y;
            As[kq * 4 + 2][row] = v.z;
            As[kq * 4 + 3][row] = v.w;
        }
#pragma unroll
        for (int j = 0; j < 4; j++) {
            int idx = tid + j * 256;
            int col = idx & 127;
            int kq  = idx >> 7;
            float4 v = *reinterpret_cast<const float4*>(
                Wp + (size_t)(bn + col) * wstride + k0 + kq * 4);
            Bs[kq * 4 + 0][col] = v.x;
            Bs[kq * 4 + 1][col] = v.y;
            Bs[kq * 4 + 2][col] = v.z;
            Bs[kq * 4 + 3][col] = v.w;
        }
        __syncthreads();

#pragma unroll
        for (int k = 0; k < 32; k++) {
            const ulonglong2* ap = reinterpret_cast<const ulonglong2*>(&As[k][ty * 8]);
            ulonglong2 a01 = ap[0];
            ulonglong2 a23 = ap[1];
            float4 b0 = *reinterpret_cast<const float4*>(&Bs[k][tx * 8]);
            float4 b1 = *reinterpret_cast<const float4*>(&Bs[k][tx * 8 + 4]);
            u64 bs[8];
            SPLAT2(bs[0], b0.x); SPLAT2(bs[1], b0.y);
            SPLAT2(bs[2], b0.z); SPLAT2(bs[3], b0.w);
            SPLAT2(bs[4], b1.x); SPLAT2(bs[5], b1.y);
            SPLAT2(bs[6], b1.z); SPLAT2(bs[7], b1.w);
            u64 apair[4] = {a01.x, a01.y, a23.x, a23.y};
#pragma unroll
            for (int r = 0; r < 4; r++)
#pragma unroll
                for (int c = 0; c < 8; c++)
                    FMA2(acc2[r][c], apair[r], bs[c]);
        }
        __syncthreads();
    }

    // epilogue: C = acc + D, in place
#pragma unroll
    for (int r = 0; r < 4; r++) {
#pragma unroll
        for (int par = 0; par < 2; par++) {
            int m  = bm + ty * 8 + 2 * r + par;
            int rr = m >> 4;
            int bb = m & 15;
            size_t slot = (mode == 0) ? (size_t)(s * rr + s - 1)
                                      : (size_t)(s * rr + s / 2 - 1);
            float* crow = out + slot * BH + (size_t)bb * 512 + bn + tx * 8;
#pragma unroll
            for (int c = 0; c < 8; c++) {
                uint32_t lo, hi;
                asm("mov.b64 {%0, %1}, %2;" : "=r"(lo), "=r"(hi) : "l"(acc2[r][c]));
                float v = par ? __uint_as_float(hi) : __uint_as_float(lo);
                crow[c] = v + crow[c];
            }
        }
    }
}

// ---------------------------------------------------------------------------
// Kernel 3: cluster scan — proven protocol, 256 rounds with W8:
//   h_{8t+7} = W8 @ h_{8t-1} + c3_t ; c3_t lives in out[8t+7] (overwritten).
// ---------------------------------------------------------------------------
__global__ void __cluster_dims__(CLUSTER, 1, 1) __launch_bounds__(512, 1)
scan_kernel(const float* __restrict__ state,   // [16][512]
            float* __restrict__ out)           // [T][16][512] + last [16][512]
{
    __shared__ float hsh[2][512];              // double-buffered h
    __shared__ float red[8][65];               // k-split partials
    __shared__ __align__(8) u64 mbar[2];       // full[buf] barriers

    const int tid  = threadIdx.x;
    const int col  = tid & 63;
    const int ks   = tid >> 6;                 // k in [ks*64, ks*64+64)
    const int rank = blockIdx.x & (CLUSTER - 1);
    const int b    = blockIdx.x / CLUSTER;     // batch
    const int c0   = rank * 64;
    const int gcol = c0 + col;

    // ---- W8 slice into registers (f32x2-packed over k) ----
    u64 wreg[32];
    {
        const u64* wp = reinterpret_cast<const u64*>(
            g_W8 + (size_t)gcol * 512 + ks * 64);
#pragma unroll
        for (int j = 0; j < 32; j += 2) {
            ulonglong2 v = *reinterpret_cast<const ulonglong2*>(wp + j);
            wreg[j]     = v.x;
            wreg[j + 1] = v.y;
        }
    }

    // ---- init: h_{-1} = state, barriers, cluster-wide visibility ----
    hsh[0][tid] = state[(size_t)b * 512 + tid];
    const uint32_t bar0 = smem_u32(&mbar[0]);
    const uint32_t bar1 = smem_u32(&mbar[1]);
    if (tid == 0) {
        asm volatile("mbarrier.init.shared.b64 [%0], 1;" :: "r"(bar0) : "memory");
        asm volatile("mbarrier.init.shared.b64 [%0], 1;" :: "r"(bar1) : "memory");
    }
    __syncthreads();
    asm volatile("barrier.cluster.arrive.aligned;" ::: "memory");
    asm volatile("barrier.cluster.wait.aligned;" ::: "memory");

    // ---- prefetch c3_0 (slot 7) ----
    float xp = 0.f;
    if (tid < 64)
        xp = __ldcg(out + (size_t)7 * BH + (size_t)b * HH + c0 + tid);

    const uint32_t laddr_h0 = smem_u32(&hsh[0][gcol]);
    const uint32_t laddr_h1 = smem_u32(&hsh[1][gcol]);

#pragma unroll 1
    for (int t = 0; t < RR; t++) {
        const int rb = t & 1;
        const uint32_t barw = rb ? bar1 : bar0;

        // ---- 1. wait for h from all 8 CTAs (2048 tx bytes) ----
        if (t > 0) {
            if (tid == 0)
                asm volatile("mbarrier.arrive.expect_tx.shared.b64 _, [%0], 2048;"
                             :: "r"(barw) : "memory");
            const uint32_t parity = ((unsigned)(t - 1) >> 1) & 1u;
            uint32_t done;
            asm volatile(
                "{\n\t.reg .pred p;\n\t"
                "mbarrier.try_wait.parity.acquire.cta.shared::cta.b64 p, [%1], %2;\n\t"
                "selp.b32 %0, 1, 0, p;\n\t}"
                : "=r"(done) : "r"(barw), "r"(parity) : "memory");
            while (!done) {
                asm volatile(
                    "{\n\t.reg .pred p;\n\t"
                    "mbarrier.try_wait.parity.acquire.cta.shared::cta.b64 p, [%1], %2, 0x989680;\n\t"
                    "selp.b32 %0, 1, 0, p;\n\t}"
                    : "=r"(done) : "r"(barw), "r"(parity) : "memory");
            }
        }

        // ---- 2. compute: packed f32x2 dot over this thread's 64 k's ----
        u64 accp = 0ull;
        const u64* hp = reinterpret_cast<const u64*>(&hsh[rb][ks * 64]);
#pragma unroll
        for (int j = 0; j < 32; j += 2) {
            ulonglong2 h2 = *reinterpret_cast<const ulonglong2*>(hp + j);
            FMA2(accp, wreg[j],     h2.x);
            FMA2(accp, wreg[j + 1], h2.y);
        }
        {
            uint32_t lo, hi;
            asm("mov.b64 {%0, %1}, %2;" : "=r"(lo), "=r"(hi) : "l"(accp));
            red[ks][col] = __uint_as_float(lo) + __uint_as_float(hi);
        }
        __syncthreads();

        // ---- 3. finalize (tid<64): reduce, publish via st.async, store out ----
        if (tid < 64) {
            float s = 0.f;
#pragma unroll
            for (int r = 0; r < 8; r++) s += red[r][tid];
            const float hn = s + xp;

            if (t + 1 < RR) {
                const uint32_t ldst = rb ? laddr_h0 : laddr_h1;
                const uint32_t lbar = rb ? bar0 : bar1;
#pragma unroll
                for (int r = 0; r < CLUSTER; r++) {
                    uint32_t raddr, rbar;
                    asm volatile("mapa.shared::cluster.u32 %0, %1, %2;"
                                 : "=r"(raddr) : "r"(ldst), "r"(r));
                    asm volatile("mapa.shared::cluster.u32 %0, %1, %2;"
                                 : "=r"(rbar) : "r"(lbar), "r"(r));
                    asm volatile(
                        "st.async.weak.shared::cluster.mbarrier::complete_tx::bytes.f32 [%0], %1, [%2];"
                        :: "r"(raddr), "f"(hn), "r"(rbar) : "memory");
                }
            }

            // out[8t+7] = h_{8t+7}
            const size_t off = (size_t)(8 * t + 7) * BH + (size_t)b * HH + c0 + tid;
            __stcg(out + off, hn);
            if (t == RR - 1)
                __stcg(out + (size_t)TT * BH + (size_t)b * HH + c0 + tid, hn);
            // prefetch c3_{t+1} from out[8t+15]
            if (t + 1 < RR)
                xp = __ldcg(out + (size_t)(8 * t + 15) * BH + (size_t)b * HH + c0 + tid);
        }
    }

    // ---- drain ----
    asm volatile("barrier.cluster.arrive.aligned;" ::: "memory");
    asm volatile("barrier.cluster.wait.aligned;" ::: "memory");
}

// ---------------------------------------------------------------------------
// Launch: xproj -> W2 -> W4 -> W8 -> pre(2) -> pre(4) -> pre(8) ->
//         scan (256 rounds, W8) -> post(8) -> post(4) -> post(2).
// ---------------------------------------------------------------------------
extern "C" void kernel_launch(void* const* d_in, const int* in_sizes, int n_in,
                              void* d_out, int out_size) {
    const float* inputs = (const float*)d_in[0];  // [T][B][I]
    const float* state  = (const float*)d_in[1];  // [B][H]
    const float* weight = (const float*)d_in[2];  // [H][I+H]
    const float* bias   = (const float*)d_in[3];  // [H]
    float* out = (float*)d_out;                   // [T][B][H] outputs, then [B][H] last

    float* W2 = nullptr; float* W4 = nullptr; float* W8 = nullptr;
    cudaGetSymbolAddress((void**)&W2, g_W2);
    cudaGetSymbolAddress((void**)&W4, g_W4);
    cudaGetSymbolAddress((void**)&W8, g_W8);

    dim3 g1(256, 4);   // M=32768 / 128, N=512 / 128
    xproj_kernel<<<g1, 256>>>(inputs, weight, bias, out);

    dim3 gw(8, 8);     // 512/64 x 512/64
    mat_sq_kernel<<<gw, 256>>>(weight, 1024, W2);  // W2 = Whh^2
    mat_sq_kernel<<<gw, 256>>>(W2, 512, W4);       // W4 = W2^2
    mat_sq_kernel<<<gw, 256>>>(W4, 512, W8);       // W8 = W4^2

    dim3 g16k(128, 4); // M=16384 / 128
    dim3 g8k(64, 4);   // M=8192 / 128
    dim3 g4k(32, 4);   // M=4096 / 128

    rec_gemm_kernel<<<g16k, 256>>>(weight, 1024, state, out, 0, 2);  // pre1
    rec_gemm_kernel<<<g8k,  256>>>(W2, 512, state, out, 0, 4);       // pre2
    rec_gemm_kernel<<<g4k,  256>>>(W4, 512, state, out, 0, 8);       // pre3

    scan_kernel<<<BB * CLUSTER, 512>>>(state, out);                  // 256 rounds, W8

    rec_gemm_kernel<<<g4k,  256>>>(W4, 512, state, out, 1, 8);       // post s=8
    rec_gemm_kernel<<<g8k,  256>>>(W2, 512, state, out, 1, 4);       // post s=4
    rec_gemm_kernel<<<g16k, 256>>>(weight, 1024, state, out, 1, 2);  // post s=2

    (void)in_sizes; (void)n_in; (void)out_size;
}

// round 13
// speedup vs baseline: 1.1600x; 1.1600x over previous
#include <cuda_runtime.h>
#include <cuda_bf16.h>
#include <cstdint>

typedef unsigned long long u64;

// Problem dims
#define TT 2048
#define BB 16
#define II 512
#define HH 512
#define BH (BB*HH)   // 8192
#define RR (TT/8)    // 256 scan rounds (8-step blocking)

#define CLUSTER 8    // CTAs per cluster = 1 batch per cluster, 64 cols per CTA

// Scratch: W^2, W^4, W^8, row-major [512][512]. Static __device__ (legal).
__device__ float g_W2[HH * HH];
__device__ float g_W4[HH * HH];
__device__ float g_W8[HH * HH];

static __device__ __forceinline__ uint32_t smem_u32(const void* p) {
    uint32_t a;
    asm("{ .reg .u64 t; cvta.to.shared.u64 t, %1; cvt.u32.u64 %0, t; }"
        : "=r"(a) : "l"(p));
    return a;
}

#define FMA2(acc, a, b) \
    asm("fma.rn.f32x2 %0, %1, %2, %0;" : "+l"(acc) : "l"(a), "l"(b))
#define SPLAT2(dst, f) \
    asm("mov.b64 %0, {%1, %1};" : "=l"(dst) : "r"(__float_as_uint(f)))

// ---------------------------------------------------------------------------
// Kernel 1: x_proj. R11-proven 128x64 tile, 256 threads, 8x4 f32x2 microtile.
// ---------------------------------------------------------------------------
__global__ __launch_bounds__(256)
void xproj_kernel(const float* __restrict__ A,      // inputs [M][512]
                  const float* __restrict__ W,      // weight [512][1024]
                  const float* __restrict__ bias,   // [512]
                  float* __restrict__ out)          // [M][512]
{
    __shared__ float As[32][132];
    __shared__ float Bs[32][68];

    const int tid = threadIdx.x;
    const int bm = blockIdx.x * 128;
    const int bn = blockIdx.y * 64;

    const int tx = tid & 15;
    const int ty = tid >> 4;

    u64 acc2[4][4];   // [m-pair][col]
#pragma unroll
    for (int r = 0; r < 4; r++)
#pragma unroll
        for (int c = 0; c < 4; c++) acc2[r][c] = 0ull;

#pragma unroll 1
    for (int kt = 0; kt < 16; kt++) {
        const int k0 = kt * 32;
#pragma unroll
        for (int j = 0; j < 4; j++) {
            int idx = tid + j * 256;
            int row = idx >> 3;
            int q   = idx & 7;
            float4 v = *reinterpret_cast<const float4*>(&A[(size_t)(bm + row) * 512 + k0 + q * 4]);
            As[q * 4 + 0][row] = v.x;
            As[q * 4 + 1][row] = v.y;
            As[q * 4 + 2][row] = v.z;
            As[q * 4 + 3][row] = v.w;
        }
#pragma unroll
        for (int j = 0; j < 2; j++) {
            int idx = tid + j * 256;
            int row = idx >> 3;
            int q   = idx & 7;
            float4 v = *reinterpret_cast<const float4*>(&W[(size_t)(bn + row) * 1024 + 512 + k0 + q * 4]);
            Bs[q * 4 + 0][row] = v.x;
            Bs[q * 4 + 1][row] = v.y;
            Bs[q * 4 + 2][row] = v.z;
            Bs[q * 4 + 3][row] = v.w;
        }
        __syncthreads();

#pragma unroll
        for (int k = 0; k < 32; k++) {
            const ulonglong2* ap = reinterpret_cast<const ulonglong2*>(&As[k][ty * 8]);
            ulonglong2 a01 = ap[0];
            ulonglong2 a23 = ap[1];
            float4 b = *reinterpret_cast<const float4*>(&Bs[k][tx * 4]);
            u64 bs[4];
            SPLAT2(bs[0], b.x); SPLAT2(bs[1], b.y);
            SPLAT2(bs[2], b.z); SPLAT2(bs[3], b.w);
            u64 apair[4] = {a01.x, a01.y, a23.x, a23.y};
#pragma unroll
            for (int r = 0; r < 4; r++)
#pragma unroll
                for (int c = 0; c < 4; c++)
                    FMA2(acc2[r][c], apair[r], bs[c]);
        }
        __syncthreads();
    }

#pragma unroll
    for (int r = 0; r < 4; r++) {
        size_t row0 = (size_t)(bm + ty * 8 + 2 * r) * 512 + bn + tx * 4;
#pragma unroll
        for (int c = 0; c < 4; c++) {
            uint32_t lo, hi;
            asm("mov.b64 {%0, %1}, %2;" : "=r"(lo), "=r"(hi) : "l"(acc2[r][c]));
            float bv = bias[bn + tx * 4 + c];
            out[row0 + c]       = __uint_as_float(lo) + bv;
            out[row0 + 512 + c] = __uint_as_float(hi) + bv;
        }
    }
}

// ---------------------------------------------------------------------------
// Kernel 1b: matrix squaring: dst = src @ src (rows stride sstride; w_hh is
// cols [0,512)). 64x64 tiles, 256 threads, 4x4 microtile. R11-proven body.
// ---------------------------------------------------------------------------
__global__ __launch_bounds__(256)
void mat_sq_kernel(const float* __restrict__ src, int sstride,
                   float* __restrict__ dst)
{
    __shared__ float As[32][68];   // [j][i]
    __shared__ float Bs[32][68];   // [j][k]

    const int tid = threadIdx.x;
    const int i0 = blockIdx.x * 64;
    const int k0g = blockIdx.y * 64;

    const int tx = tid & 15;
    const int ty = tid >> 4;

    float acc[4][4];
#pragma unroll
    for (int a = 0; a < 4; a++)
#pragma unroll
        for (int b = 0; b < 4; b++) acc[a][b] = 0.f;

#pragma unroll 1
    for (int jt = 0; jt < 16; jt++) {
        const int j0 = jt * 32;
        // A tile: 64 i-rows x 32 j (transposed into As[j][i])
#pragma unroll
        for (int l = 0; l < 2; l++) {
            int idx = tid + l * 256;
            int row = idx >> 3;            // 0..63
            int q   = idx & 7;
            float4 v = *reinterpret_cast<const float4*>(
                src + (size_t)(i0 + row) * sstride + j0 + q * 4);
            As[q * 4 + 0][row] = v.x;
            As[q * 4 + 1][row] = v.y;
            As[q * 4 + 2][row] = v.z;
            As[q * 4 + 3][row] = v.w;
        }
        // B tile: 32 j-rows x 64 k
#pragma unroll
        for (int l = 0; l < 2; l++) {
            int idx = tid + l * 256;
            int jr  = idx >> 4;            // 0..31
            int q   = idx & 15;
            float4 v = *reinterpret_cast<const float4*>(
                src + (size_t)(j0 + jr) * sstride + k0g + q * 4);
            Bs[jr][q * 4 + 0] = v.x;
            Bs[jr][q * 4 + 1] = v.y;
            Bs[jr][q * 4 + 2] = v.z;
            Bs[jr][q * 4 + 3] = v.w;
        }
        __syncthreads();

#pragma unroll
        for (int j = 0; j < 32; j++) {
            float a[4], b[4];
#pragma unroll
            for (int x = 0; x < 4; x++) a[x] = As[j][ty * 4 + x];
#pragma unroll
            for (int x = 0; x < 4; x++) b[x] = Bs[j][tx * 4 + x];
#pragma unroll
            for (int x = 0; x < 4; x++)
#pragma unroll
                for (int y = 0; y < 4; y++)
                    acc[x][y] = fmaf(a[x], b[y], acc[x][y]);
        }
        __syncthreads();
    }

#pragma unroll
    for (int x = 0; x < 4; x++)
#pragma unroll
        for (int y = 0; y < 4; y++)
            dst[(size_t)(i0 + ty * 4 + x) * 512 + k0g + tx * 4 + y] = acc[x][y];
}

// ---------------------------------------------------------------------------
// Kernel 2: recurrent-side parallel GEMMs. R11-proven 128x64 tile body,
// parameterized by (mode, s). Row m -> (rr = m>>4, bb = m&15).
//  pre  (mode 0): A slot = s*rr + s/2-1 ; D slot = s*rr + s-1
//  post (mode 1): A = (rr==0 ? state : slot s*rr-1) ; D slot = s*rr + s/2-1
// ---------------------------------------------------------------------------
__global__ __launch_bounds__(256)
void rec_gemm_kernel(const float* __restrict__ Wp, int wstride,
                     const float* __restrict__ state,  // [16][512]
                     float* __restrict__ out,
                     int mode, int s)
{
    __shared__ float As[32][132];
    __shared__ float Bs[32][68];

    const int tid = threadIdx.x;
    const int bm = blockIdx.x * 128;
    const int bn = blockIdx.y * 64;

    const int tx = tid & 15;
    const int ty = tid >> 4;

    u64 acc2[4][4];
#pragma unroll
    for (int r = 0; r < 4; r++)
#pragma unroll
        for (int c = 0; c < 4; c++) acc2[r][c] = 0ull;

#pragma unroll 1
    for (int kt = 0; kt < 16; kt++) {
        const int k0 = kt * 32;
#pragma unroll
        for (int j = 0; j < 4; j++) {
            int idx = tid + j * 256;
            int row = idx >> 3;
            int q   = idx & 7;
            int m   = bm + row;
            int rr  = m >> 4;
            int bb  = m & 15;
            const float* arow;
            if (mode == 0) {
                arow = out + (size_t)(s * rr + s / 2 - 1) * BH + (size_t)bb * 512;
            } else {
                arow = (rr == 0) ? (state + (size_t)bb * 512)
                                 : (out + (size_t)(s * rr - 1) * BH + (size_t)bb * 512);
            }
            float4 v = *reinterpret_cast<const float4*>(arow + k0 + q * 4);
            As[q * 4 + 0][row] = v.x;
            As[q * 4 + 1][row] = v.y;
            As[q * 4 + 2][row] = v.z;
            As[q * 4 + 3][row] = v.w;
        }
#pragma unroll
        for (int j = 0; j < 2; j++) {
            int idx = tid + j * 256;
            int row = idx >> 3;
            int q   = idx & 7;
            float4 v = *reinterpret_cast<const float4*>(
                Wp + (size_t)(bn + row) * wstride + k0 + q * 4);
            Bs[q * 4 + 0][row] = v.x;
            Bs[q * 4 + 1][row] = v.y;
            Bs[q * 4 + 2][row] = v.z;
            Bs[q * 4 + 3][row] = v.w;
        }
        __syncthreads();

#pragma unroll
        for (int k = 0; k < 32; k++) {
            const ulonglong2* ap = reinterpret_cast<const ulonglong2*>(&As[k][ty * 8]);
            ulonglong2 a01 = ap[0];
            ulonglong2 a23 = ap[1];
            float4 b = *reinterpret_cast<const float4*>(&Bs[k][tx * 4]);
            u64 bs[4];
            SPLAT2(bs[0], b.x); SPLAT2(bs[1], b.y);
            SPLAT2(bs[2], b.z); SPLAT2(bs[3], b.w);
            u64 apair[4] = {a01.x, a01.y, a23.x, a23.y};
#pragma unroll
            for (int r = 0; r < 4; r++)
#pragma unroll
                for (int c = 0; c < 4; c++)
                    FMA2(acc2[r][c], apair[r], bs[c]);
        }
        __syncthreads();
    }

    // epilogue: C = acc + D, in place
#pragma unroll
    for (int r = 0; r < 4; r++) {
#pragma unroll
        for (int par = 0; par < 2; par++) {
            int m  = bm + ty * 8 + 2 * r + par;
            int rr = m >> 4;
            int bb = m & 15;
            size_t slot = (mode == 0) ? (size_t)(s * rr + s - 1)
                                      : (size_t)(s * rr + s / 2 - 1);
            float* crow = out + slot * BH + (size_t)bb * 512 + bn + tx * 4;
#pragma unroll
            for (int c = 0; c < 4; c++) {
                uint32_t lo, hi;
                asm("mov.b64 {%0, %1}, %2;" : "=r"(lo), "=r"(hi) : "l"(acc2[r][c]));
                float v = par ? __uint_as_float(hi) : __uint_as_float(lo);
                crow[c] = v + crow[c];
            }
        }
    }
}

// ---------------------------------------------------------------------------
// Kernel 3: cluster scan — proven protocol, 256 rounds with W8 (R12 body):
//   h_{8t+7} = W8 @ h_{8t-1} + c3_t ; c3_t lives in out[8t+7] (overwritten).
// ---------------------------------------------------------------------------
__global__ void __cluster_dims__(CLUSTER, 1, 1) __launch_bounds__(512, 1)
scan_kernel(const float* __restrict__ state,   // [16][512]
            float* __restrict__ out)           // [T][16][512] + last [16][512]
{
    __shared__ float hsh[2][512];              // double-buffered h
    __shared__ float red[8][65];               // k-split partials
    __shared__ __align__(8) u64 mbar[2];       // full[buf] barriers

    const int tid  = threadIdx.x;
    const int col  = tid & 63;
    const int ks   = tid >> 6;                 // k in [ks*64, ks*64+64)
    const int rank = blockIdx.x & (CLUSTER - 1);
    const int b    = blockIdx.x / CLUSTER;     // batch
    const int c0   = rank * 64;
    const int gcol = c0 + col;

    // ---- W8 slice into registers (f32x2-packed over k) ----
    u64 wreg[32];
    {
        const u64* wp = reinterpret_cast<const u64*>(
            g_W8 + (size_t)gcol * 512 + ks * 64);
#pragma unroll
        for (int j = 0; j < 32; j += 2) {
            ulonglong2 v = *reinterpret_cast<const ulonglong2*>(wp + j);
            wreg[j]     = v.x;
            wreg[j + 1] = v.y;
        }
    }

    // ---- init: h_{-1} = state, barriers, cluster-wide visibility ----
    hsh[0][tid] = state[(size_t)b * 512 + tid];
    const uint32_t bar0 = smem_u32(&mbar[0]);
    const uint32_t bar1 = smem_u32(&mbar[1]);
    if (tid == 0) {
        asm volatile("mbarrier.init.shared.b64 [%0], 1;" :: "r"(bar0) : "memory");
        asm volatile("mbarrier.init.shared.b64 [%0], 1;" :: "r"(bar1) : "memory");
    }
    __syncthreads();
    asm volatile("barrier.cluster.arrive.aligned;" ::: "memory");
    asm volatile("barrier.cluster.wait.aligned;" ::: "memory");

    // ---- prefetch c3_0 (slot 7) ----
    float xp = 0.f;
    if (tid < 64)
        xp = __ldcg(out + (size_t)7 * BH + (size_t)b * HH + c0 + tid);

    const uint32_t laddr_h0 = smem_u32(&hsh[0][gcol]);
    const uint32_t laddr_h1 = smem_u32(&hsh[1][gcol]);

#pragma unroll 1
    for (int t = 0; t < RR; t++) {
        const int rb = t & 1;
        const uint32_t barw = rb ? bar1 : bar0;

        // ---- 1. wait for h from all 8 CTAs (2048 tx bytes) ----
        if (t > 0) {
            if (tid == 0)
                asm volatile("mbarrier.arrive.expect_tx.shared.b64 _, [%0], 2048;"
                             :: "r"(barw) : "memory");
            const uint32_t parity = ((unsigned)(t - 1) >> 1) & 1u;
            uint32_t done;
            asm volatile(
                "{\n\t.reg .pred p;\n\t"
                "mbarrier.try_wait.parity.acquire.cta.shared::cta.b64 p, [%1], %2;\n\t"
                "selp.b32 %0, 1, 0, p;\n\t}"
                : "=r"(done) : "r"(barw), "r"(parity) : "memory");
            while (!done) {
                asm volatile(
                    "{\n\t.reg .pred p;\n\t"
                    "mbarrier.try_wait.parity.acquire.cta.shared::cta.b64 p, [%1], %2, 0x989680;\n\t"
                    "selp.b32 %0, 1, 0, p;\n\t}"
                    : "=r"(done) : "r"(barw), "r"(parity) : "memory");
            }
        }

        // ---- 2. compute: packed f32x2 dot over this thread's 64 k's ----
        u64 accp = 0ull;
        const u64* hp = reinterpret_cast<const u64*>(&hsh[rb][ks * 64]);
#pragma unroll
        for (int j = 0; j < 32; j += 2) {
            ulonglong2 h2 = *reinterpret_cast<const ulonglong2*>(hp + j);
            FMA2(accp, wreg[j],     h2.x);
            FMA2(accp, wreg[j + 1], h2.y);
        }
        {
            uint32_t lo, hi;
            asm("mov.b64 {%0, %1}, %2;" : "=r"(lo), "=r"(hi) : "l"(accp));
            red[ks][col] = __uint_as_float(lo) + __uint_as_float(hi);
        }
        __syncthreads();

        // ---- 3. finalize (tid<64): reduce, publish via st.async, store out ----
        if (tid < 64) {
            float s = 0.f;
#pragma unroll
            for (int r = 0; r < 8; r++) s += red[r][tid];
            const float hn = s + xp;

            if (t + 1 < RR) {
                const uint32_t ldst = rb ? laddr_h0 : laddr_h1;
                const uint32_t lbar = rb ? bar0 : bar1;
#pragma unroll
                for (int r = 0; r < CLUSTER; r++) {
                    uint32_t raddr, rbar;
                    asm volatile("mapa.shared::cluster.u32 %0, %1, %2;"
                                 : "=r"(raddr) : "r"(ldst), "r"(r));
                    asm volatile("mapa.shared::cluster.u32 %0, %1, %2;"
                                 : "=r"(rbar) : "r"(lbar), "r"(r));
                    asm volatile(
                        "st.async.weak.shared::cluster.mbarrier::complete_tx::bytes.f32 [%0], %1, [%2];"
                        :: "r"(raddr), "f"(hn), "r"(rbar) : "memory");
                }
            }

            // out[8t+7] = h_{8t+7}
            const size_t off = (size_t)(8 * t + 7) * BH + (size_t)b * HH + c0 + tid;
            __stcg(out + off, hn);
            if (t == RR - 1)
                __stcg(out + (size_t)TT * BH + (size_t)b * HH + c0 + tid, hn);
            // prefetch c3_{t+1} from out[8t+15]
            if (t + 1 < RR)
                xp = __ldcg(out + (size_t)(8 * t + 15) * BH + (size_t)b * HH + c0 + tid);
        }
    }

    // ---- drain ----
    asm volatile("barrier.cluster.arrive.aligned;" ::: "memory");
    asm volatile("barrier.cluster.wait.aligned;" ::: "memory");
}

// ---------------------------------------------------------------------------
// Launch: xproj -> W2 -> W4 -> W8 -> pre(2) -> pre(4) -> pre(8) ->
//         scan (256 rounds, W8) -> post(8) -> post(4) -> post(2).
// ---------------------------------------------------------------------------
extern "C" void kernel_launch(void* const* d_in, const int* in_sizes, int n_in,
                              void* d_out, int out_size) {
    const float* inputs = (const float*)d_in[0];  // [T][B][I]
    const float* state  = (const float*)d_in[1];  // [B][H]
    const float* weight = (const float*)d_in[2];  // [H][I+H]
    const float* bias   = (const float*)d_in[3];  // [H]
    float* out = (float*)d_out;                   // [T][B][H] outputs, then [B][H] last

    float* W2 = nullptr; float* W4 = nullptr; float* W8 = nullptr;
    cudaGetSymbolAddress((void**)&W2, g_W2);
    cudaGetSymbolAddress((void**)&W4, g_W4);
    cudaGetSymbolAddress((void**)&W8, g_W8);

    dim3 g1(256, 8);   // M=32768 / 128, N=512 / 64
    xproj_kernel<<<g1, 256>>>(inputs, weight, bias, out);

    dim3 gw(8, 8);     // 512/64 x 512/64
    mat_sq_kernel<<<gw, 256>>>(weight, 1024, W2);  // W2 = Whh^2
    mat_sq_kernel<<<gw, 256>>>(W2, 512, W4);       // W4 = W2^2
    mat_sq_kernel<<<gw, 256>>>(W4, 512, W8);       // W8 = W4^2

    dim3 g16k(128, 8); // M=16384 / 128
    dim3 g8k(64, 8);   // M=8192 / 128
    dim3 g4k(32, 8);   // M=4096 / 128

    rec_gemm_kernel<<<g16k, 256>>>(weight, 1024, state, out, 0, 2);  // pre s=2
    rec_gemm_kernel<<<g8k,  256>>>(W2, 512, state, out, 0, 4);       // pre s=4
    rec_gemm_kernel<<<g4k,  256>>>(W4, 512, state, out, 0, 8);       // pre s=8

    scan_kernel<<<BB * CLUSTER, 512>>>(state, out);                  // 256 rounds, W8

    rec_gemm_kernel<<<g4k,  256>>>(W4, 512, state, out, 1, 8);       // post s=8
    rec_gemm_kernel<<<g8k,  256>>>(W2, 512, state, out, 1, 4);       // post s=4
    rec_gemm_kernel<<<g16k, 256>>>(weight, 1024, state, out, 1, 2);  // post s=2

    (void)in_sizes; (void)n_in; (void)out_size;
}

// round 14
// speedup vs baseline: 1.2392x; 1.0683x over previous
#include <cuda_runtime.h>
#include <cuda_bf16.h>
#include <cstdint>

typedef unsigned long long u64;

// Problem dims
#define TT 2048
#define BB 16
#define II 512
#define HH 512
#define BH (BB*HH)   // 8192
#define RR (TT/16)   // 128 scan rounds (16-step blocking)

#define CLUSTER 8    // CTAs per cluster = 1 batch per cluster, 64 cols per CTA

// Scratch: W^2..W^16, row-major [512][512]. Static __device__ (legal).
__device__ float g_W2[HH * HH];
__device__ float g_W4[HH * HH];
__device__ float g_W8[HH * HH];
__device__ float g_W16[HH * HH];

static __device__ __forceinline__ uint32_t smem_u32(const void* p) {
    uint32_t a;
    asm("{ .reg .u64 t; cvta.to.shared.u64 t, %1; cvt.u32.u64 %0, t; }"
        : "=r"(a) : "l"(p));
    return a;
}

#define FMA2(acc, a, b) \
    asm("fma.rn.f32x2 %0, %1, %2, %0;" : "+l"(acc) : "l"(a), "l"(b))
#define SPLAT2(dst, f) \
    asm("mov.b64 %0, {%1, %1};" : "=l"(dst) : "r"(__float_as_uint(f)))

// XOR swizzle: element (k, col) lives at physical column col ^ SWZ(k).
// SWZ(k) touches bits 2-4 only -> preserves 16B alignment of col%4==0 bases.
#define SWZ(kk) ((((kk) >> 2) & 7) << 2)

// ---------------------------------------------------------------------------
// Kernel 1: x_proj. 128x64 tile, 256 threads, 8x4 f32x2 microtile,
// conflict-free swizzled smem tiles.
// ---------------------------------------------------------------------------
__global__ __launch_bounds__(256)
void xproj_kernel(const float* __restrict__ A,      // inputs [M][512]
                  const float* __restrict__ W,      // weight [512][1024]
                  const float* __restrict__ bias,   // [512]
                  float* __restrict__ out)          // [M][512]
{
    __shared__ float As[32][132];
    __shared__ float Bs[32][68];

    const int tid = threadIdx.x;
    const int bm = blockIdx.x * 128;
    const int bn = blockIdx.y * 64;

    const int tx = tid & 15;
    const int ty = tid >> 4;

    u64 acc2[4][4];   // [m-pair][col]
#pragma unroll
    for (int r = 0; r < 4; r++)
#pragma unroll
        for (int c = 0; c < 4; c++) acc2[r][c] = 0ull;

#pragma unroll 1
    for (int kt = 0; kt < 16; kt++) {
        const int k0 = kt * 32;
#pragma unroll
        for (int j = 0; j < 4; j++) {
            int idx = tid + j * 256;
            int row = idx >> 3;
            int q   = idx & 7;
            int sw  = (q << 2);            // SWZ(q*4+c) = q<<2 (c<4)
            float4 v = *reinterpret_cast<const float4*>(&A[(size_t)(bm + row) * 512 + k0 + q * 4]);
            As[q * 4 + 0][row ^ sw] = v.x;
            As[q * 4 + 1][row ^ sw] = v.y;
            As[q * 4 + 2][row ^ sw] = v.z;
            As[q * 4 + 3][row ^ sw] = v.w;
        }
#pragma unroll
        for (int j = 0; j < 2; j++) {
            int idx = tid + j * 256;
            int row = idx >> 3;
            int q   = idx & 7;
            int sw  = (q << 2);
            float4 v = *reinterpret_cast<const float4*>(&W[(size_t)(bn + row) * 1024 + 512 + k0 + q * 4]);
            Bs[q * 4 + 0][row ^ sw] = v.x;
            Bs[q * 4 + 1][row ^ sw] = v.y;
            Bs[q * 4 + 2][row ^ sw] = v.z;
            Bs[q * 4 + 3][row ^ sw] = v.w;
        }
        __syncthreads();

#pragma unroll
        for (int k = 0; k < 32; k++) {
            const int s4 = SWZ(k);
            ulonglong2 a01 = *reinterpret_cast<const ulonglong2*>(&As[k][(ty * 8) ^ s4]);
            ulonglong2 a23 = *reinterpret_cast<const ulonglong2*>(&As[k][(ty * 8 + 4) ^ s4]);
            float4 b = *reinterpret_cast<const float4*>(&Bs[k][(tx * 4) ^ s4]);
            u64 bs[4];
            SPLAT2(bs[0], b.x); SPLAT2(bs[1], b.y);
            SPLAT2(bs[2], b.z); SPLAT2(bs[3], b.w);
            u64 apair[4] = {a01.x, a01.y, a23.x, a23.y};
#pragma unroll
            for (int r = 0; r < 4; r++)
#pragma unroll
                for (int c = 0; c < 4; c++)
                    FMA2(acc2[r][c], apair[r], bs[c]);
        }
        __syncthreads();
    }

#pragma unroll
    for (int r = 0; r < 4; r++) {
        size_t row0 = (size_t)(bm + ty * 8 + 2 * r) * 512 + bn + tx * 4;
#pragma unroll
        for (int c = 0; c < 4; c++) {
            uint32_t lo, hi;
            asm("mov.b64 {%0, %1}, %2;" : "=r"(lo), "=r"(hi) : "l"(acc2[r][c]));
            float bv = bias[bn + tx * 4 + c];
            out[row0 + c]       = __uint_as_float(lo) + bv;
            out[row0 + 512 + c] = __uint_as_float(hi) + bv;
        }
    }
}

// ---------------------------------------------------------------------------
// Kernel 1b: matrix squaring: dst = src @ src (rows stride sstride).
// 64x64 tiles, proven body (latency-bound, left unswizzled).
// ---------------------------------------------------------------------------
__global__ __launch_bounds__(256)
void mat_sq_kernel(const float* __restrict__ src, int sstride,
                   float* __restrict__ dst)
{
    __shared__ float As[32][68];   // [j][i]
    __shared__ float Bs[32][68];   // [j][k]

    const int tid = threadIdx.x;
    const int i0 = blockIdx.x * 64;
    const int k0g = blockIdx.y * 64;

    const int tx = tid & 15;
    const int ty = tid >> 4;

    float acc[4][4];
#pragma unroll
    for (int a = 0; a < 4; a++)
#pragma unroll
        for (int b = 0; b < 4; b++) acc[a][b] = 0.f;

#pragma unroll 1
    for (int jt = 0; jt < 16; jt++) {
        const int j0 = jt * 32;
#pragma unroll
        for (int l = 0; l < 2; l++) {
            int idx = tid + l * 256;
            int row = idx >> 3;
            int q   = idx & 7;
            float4 v = *reinterpret_cast<const float4*>(
                src + (size_t)(i0 + row) * sstride + j0 + q * 4);
            As[q * 4 + 0][row] = v.x;
            As[q * 4 + 1][row] = v.y;
            As[q * 4 + 2][row] = v.z;
            As[q * 4 + 3][row] = v.w;
        }
#pragma unroll
        for (int l = 0; l < 2; l++) {
            int idx = tid + l * 256;
            int jr  = idx >> 4;
            int q   = idx & 15;
            float4 v = *reinterpret_cast<const float4*>(
                src + (size_t)(j0 + jr) * sstride + k0g + q * 4);
            Bs[jr][q * 4 + 0] = v.x;
            Bs[jr][q * 4 + 1] = v.y;
            Bs[jr][q * 4 + 2] = v.z;
            Bs[jr][q * 4 + 3] = v.w;
        }
        __syncthreads();

#pragma unroll
        for (int j = 0; j < 32; j++) {
            float a[4], b[4];
#pragma unroll
            for (int x = 0; x < 4; x++) a[x] = As[j][ty * 4 + x];
#pragma unroll
            for (int x = 0; x < 4; x++) b[x] = Bs[j][tx * 4 + x];
#pragma unroll
            for (int x = 0; x < 4; x++)
#pragma unroll
                for (int y = 0; y < 4; y++)
                    acc[x][y] = fmaf(a[x], b[y], acc[x][y]);
        }
        __syncthreads();
    }

#pragma unroll
    for (int x = 0; x < 4; x++)
#pragma unroll
        for (int y = 0; y < 4; y++)
            dst[(size_t)(i0 + ty * 4 + x) * 512 + k0g + tx * 4 + y] = acc[x][y];
}

// ---------------------------------------------------------------------------
// Kernel 2: recurrent-side parallel GEMMs, swizzled 128x64 tile.
// Row m -> (rr = m>>4, bb = m&15). Level s in {2,4,8,16}:
//  pre  (mode 0): A slot = s*rr + s/2-1 ; D slot = s*rr + s-1
//  post (mode 1): A = (rr==0 ? state : slot s*rr-1) ; D slot = s*rr + s/2-1
// ---------------------------------------------------------------------------
__global__ __launch_bounds__(256)
void rec_gemm_kernel(const float* __restrict__ Wp, int wstride,
                     const float* __restrict__ state,  // [16][512]
                     float* __restrict__ out,
                     int mode, int s)
{
    __shared__ float As[32][132];
    __shared__ float Bs[32][68];

    const int tid = threadIdx.x;
    const int bm = blockIdx.x * 128;
    const int bn = blockIdx.y * 64;

    const int tx = tid & 15;
    const int ty = tid >> 4;

    u64 acc2[4][4];
#pragma unroll
    for (int r = 0; r < 4; r++)
#pragma unroll
        for (int c = 0; c < 4; c++) acc2[r][c] = 0ull;

#pragma unroll 1
    for (int kt = 0; kt < 16; kt++) {
        const int k0 = kt * 32;
#pragma unroll
        for (int j = 0; j < 4; j++) {
            int idx = tid + j * 256;
            int row = idx >> 3;
            int q   = idx & 7;
            int sw  = (q << 2);
            int m   = bm + row;
            int rr  = m >> 4;
            int bb  = m & 15;
            const float* arow;
            if (mode == 0) {
                arow = out + (size_t)(s * rr + s / 2 - 1) * BH + (size_t)bb * 512;
            } else {
                arow = (rr == 0) ? (state + (size_t)bb * 512)
                                 : (out + (size_t)(s * rr - 1) * BH + (size_t)bb * 512);
            }
            float4 v = *reinterpret_cast<const float4*>(arow + k0 + q * 4);
            As[q * 4 + 0][row ^ sw] = v.x;
            As[q * 4 + 1][row ^ sw] = v.y;
            As[q * 4 + 2][row ^ sw] = v.z;
            As[q * 4 + 3][row ^ sw] = v.w;
        }
#pragma unroll
        for (int j = 0; j < 2; j++) {
            int idx = tid + j * 256;
            int row = idx >> 3;
            int q   = idx & 7;
            int sw  = (q << 2);
            float4 v = *reinterpret_cast<const float4*>(
                Wp + (size_t)(bn + row) * wstride + k0 + q * 4);
            Bs[q * 4 + 0][row ^ sw] = v.x;
            Bs[q * 4 + 1][row ^ sw] = v.y;
            Bs[q * 4 + 2][row ^ sw] = v.z;
            Bs[q * 4 + 3][row ^ sw] = v.w;
        }
        __syncthreads();

#pragma unroll
        for (int k = 0; k < 32; k++) {
            const int s4 = SWZ(k);
            ulonglong2 a01 = *reinterpret_cast<const ulonglong2*>(&As[k][(ty * 8) ^ s4]);
            ulonglong2 a23 = *reinterpret_cast<const ulonglong2*>(&As[k][(ty * 8 + 4) ^ s4]);
            float4 b = *reinterpret_cast<const float4*>(&Bs[k][(tx * 4) ^ s4]);
            u64 bs[4];
            SPLAT2(bs[0], b.x); SPLAT2(bs[1], b.y);
            SPLAT2(bs[2], b.z); SPLAT2(bs[3], b.w);
            u64 apair[4] = {a01.x, a01.y, a23.x, a23.y};
#pragma unroll
            for (int r = 0; r < 4; r++)
#pragma unroll
                for (int c = 0; c < 4; c++)
                    FMA2(acc2[r][c], apair[r], bs[c]);
        }
        __syncthreads();
    }

    // epilogue: C = acc + D, in place
#pragma unroll
    for (int r = 0; r < 4; r++) {
#pragma unroll
        for (int par = 0; par < 2; par++) {
            int m  = bm + ty * 8 + 2 * r + par;
            int rr = m >> 4;
            int bb = m & 15;
            size_t slot = (mode == 0) ? (size_t)(s * rr + s - 1)
                                      : (size_t)(s * rr + s / 2 - 1);
            float* crow = out + slot * BH + (size_t)bb * 512 + bn + tx * 4;
#pragma unroll
            for (int c = 0; c < 4; c++) {
                uint32_t lo, hi;
                asm("mov.b64 {%0, %1}, %2;" : "=r"(lo), "=r"(hi) : "l"(acc2[r][c]));
                float v = par ? __uint_as_float(hi) : __uint_as_float(lo);
                crow[c] = v + crow[c];
            }
        }
    }
}

// ---------------------------------------------------------------------------
// Kernel 3: cluster scan — proven protocol, 128 rounds with W16:
//   h_{16t+15} = W16 @ h_{16t-1} + c4_t ; c4_t in out[16t+15] (overwritten).
// ---------------------------------------------------------------------------
__global__ void __cluster_dims__(CLUSTER, 1, 1) __launch_bounds__(512, 1)
scan_kernel(const float* __restrict__ state,   // [16][512]
            float* __restrict__ out)           // [T][16][512] + last [16][512]
{
    __shared__ float hsh[2][512];              // double-buffered h
    __shared__ float red[8][65];               // k-split partials
    __shared__ __align__(8) u64 mbar[2];       // full[buf] barriers

    const int tid  = threadIdx.x;
    const int col  = tid & 63;
    const int ks   = tid >> 6;                 // k in [ks*64, ks*64+64)
    const int rank = blockIdx.x & (CLUSTER - 1);
    const int b    = blockIdx.x / CLUSTER;     // batch
    const int c0   = rank * 64;
    const int gcol = c0 + col;

    // ---- W16 slice into registers (f32x2-packed over k) ----
    u64 wreg[32];
    {
        const u64* wp = reinterpret_cast<const u64*>(
            g_W16 + (size_t)gcol * 512 + ks * 64);
#pragma unroll
        for (int j = 0; j < 32; j += 2) {
            ulonglong2 v = *reinterpret_cast<const ulonglong2*>(wp + j);
            wreg[j]     = v.x;
            wreg[j + 1] = v.y;
        }
    }

    // ---- init: h_{-1} = state, barriers, cluster-wide visibility ----
    hsh[0][tid] = state[(size_t)b * 512 + tid];
    const uint32_t bar0 = smem_u32(&mbar[0]);
    const uint32_t bar1 = smem_u32(&mbar[1]);
    if (tid == 0) {
        asm volatile("mbarrier.init.shared.b64 [%0], 1;" :: "r"(bar0) : "memory");
        asm volatile("mbarrier.init.shared.b64 [%0], 1;" :: "r"(bar1) : "memory");
    }
    __syncthreads();
    asm volatile("barrier.cluster.arrive.aligned;" ::: "memory");
    asm volatile("barrier.cluster.wait.aligned;" ::: "memory");

    // ---- prefetch c4_0 (slot 15) ----
    float xp = 0.f;
    if (tid < 64)
        xp = __ldcg(out + (size_t)15 * BH + (size_t)b * HH + c0 + tid);

    const uint32_t laddr_h0 = smem_u32(&hsh[0][gcol]);
    const uint32_t laddr_h1 = smem_u32(&hsh[1][gcol]);

#pragma unroll 1
    for (int t = 0; t < RR; t++) {
        const int rb = t & 1;
        const uint32_t barw = rb ? bar1 : bar0;

        // ---- 1. wait for h from all 8 CTAs (2048 tx bytes) ----
        if (t > 0) {
            if (tid == 0)
                asm volatile("mbarrier.arrive.expect_tx.shared.b64 _, [%0], 2048;"
                             :: "r"(barw) : "memory");
            const uint32_t parity = ((unsigned)(t - 1) >> 1) & 1u;
            uint32_t done;
            asm volatile(
                "{\n\t.reg .pred p;\n\t"
                "mbarrier.try_wait.parity.acquire.cta.shared::cta.b64 p, [%1], %2;\n\t"
                "selp.b32 %0, 1, 0, p;\n\t}"
                : "=r"(done) : "r"(barw), "r"(parity) : "memory");
            while (!done) {
                asm volatile(
                    "{\n\t.reg .pred p;\n\t"
                    "mbarrier.try_wait.parity.acquire.cta.shared::cta.b64 p, [%1], %2, 0x989680;\n\t"
                    "selp.b32 %0, 1, 0, p;\n\t}"
                    : "=r"(done) : "r"(barw), "r"(parity) : "memory");
            }
        }

        // ---- 2. compute: packed f32x2 dot over this thread's 64 k's ----
        u64 accp = 0ull;
        const u64* hp = reinterpret_cast<const u64*>(&hsh[rb][ks * 64]);
#pragma unroll
        for (int j = 0; j < 32; j += 2) {
            ulonglong2 h2 = *reinterpret_cast<const ulonglong2*>(hp + j);
            FMA2(accp, wreg[j],     h2.x);
            FMA2(accp, wreg[j + 1], h2.y);
        }
        {
            uint32_t lo, hi;
            asm("mov.b64 {%0, %1}, %2;" : "=r"(lo), "=r"(hi) : "l"(accp));
            red[ks][col] = __uint_as_float(lo) + __uint_as_float(hi);
        }
        __syncthreads();

        // ---- 3. finalize (tid<64): reduce, publish via st.async, store out ----
        if (tid < 64) {
            float s = 0.f;
#pragma unroll
            for (int r = 0; r < 8; r++) s += red[r][tid];
            const float hn = s + xp;

            if (t + 1 < RR) {
                const uint32_t ldst = rb ? laddr_h0 : laddr_h1;
                const uint32_t lbar = rb ? bar0 : bar1;
#pragma unroll
                for (int r = 0; r < CLUSTER; r++) {
                    uint32_t raddr, rbar;
                    asm volatile("mapa.shared::cluster.u32 %0, %1, %2;"
                                 : "=r"(raddr) : "r"(ldst), "r"(r));
                    asm volatile("mapa.shared::cluster.u32 %0, %1, %2;"
                                 : "=r"(rbar) : "r"(lbar), "r"(r));
                    asm volatile(
                        "st.async.weak.shared::cluster.mbarrier::complete_tx::bytes.f32 [%0], %1, [%2];"
                        :: "r"(raddr), "f"(hn), "r"(rbar) : "memory");
                }
            }

            // out[16t+15] = h_{16t+15}
            const size_t off = (size_t)(16 * t + 15) * BH + (size_t)b * HH + c0 + tid;
            __stcg(out + off, hn);
            if (t == RR - 1)
                __stcg(out + (size_t)TT * BH + (size_t)b * HH + c0 + tid, hn);
            // prefetch c4_{t+1} from out[16t+31]
            if (t + 1 < RR)
                xp = __ldcg(out + (size_t)(16 * t + 31) * BH + (size_t)b * HH + c0 + tid);
        }
    }

    // ---- drain ----
    asm volatile("barrier.cluster.arrive.aligned;" ::: "memory");
    asm volatile("barrier.cluster.wait.aligned;" ::: "memory");
}

// ---------------------------------------------------------------------------
// Launch: xproj -> W2..W16 -> pre(2,4,8,16) -> scan(128 rounds, W16) ->
//         post(16,8,4,2).
// ---------------------------------------------------------------------------
extern "C" void kernel_launch(void* const* d_in, const int* in_sizes, int n_in,
                              void* d_out, int out_size) {
    const float* inputs = (const float*)d_in[0];  // [T][B][I]
    const float* state  = (const float*)d_in[1];  // [B][H]
    const float* weight = (const float*)d_in[2];  // [H][I+H]
    const float* bias   = (const float*)d_in[3];  // [H]
    float* out = (float*)d_out;                   // [T][B][H] outputs, then [B][H] last

    float *W2, *W4, *W8, *W16;
    cudaGetSymbolAddress((void**)&W2,  g_W2);
    cudaGetSymbolAddress((void**)&W4,  g_W4);
    cudaGetSymbolAddress((void**)&W8,  g_W8);
    cudaGetSymbolAddress((void**)&W16, g_W16);

    dim3 g1(256, 8);   // M=32768 / 128, N=512 / 64
    xproj_kernel<<<g1, 256>>>(inputs, weight, bias, out);

    dim3 gw(8, 8);     // 512/64 x 512/64
    mat_sq_kernel<<<gw, 256>>>(weight, 1024, W2);  // W2  = Whh^2
    mat_sq_kernel<<<gw, 256>>>(W2, 512, W4);       // W4  = W2^2
    mat_sq_kernel<<<gw, 256>>>(W4, 512, W8);       // W8  = W4^2
    mat_sq_kernel<<<gw, 256>>>(W8, 512, W16);      // W16 = W8^2

    dim3 g16k(128, 8); // M=16384 / 128
    dim3 g8k(64, 8);   // M=8192 / 128
    dim3 g4k(32, 8);   // M=4096 / 128
    dim3 g2k(16, 8);   // M=2048 / 128

    rec_gemm_kernel<<<g16k, 256>>>(weight, 1024, state, out, 0, 2);   // pre s=2
    rec_gemm_kernel<<<g8k,  256>>>(W2, 512, state, out, 0, 4);        // pre s=4
    rec_gemm_kernel<<<g4k,  256>>>(W4, 512, state, out, 0, 8);        // pre s=8
    rec_gemm_kernel<<<g2k,  256>>>(W8, 512, state, out, 0, 16);       // pre s=16

    scan_kernel<<<BB * CLUSTER, 512>>>(state, out);                   // 128 rounds, W16

    rec_gemm_kernel<<<g2k,  256>>>(W8, 512, state, out, 1, 16);       // post s=16
    rec_gemm_kernel<<<g4k,  256>>>(W4, 512, state, out, 1, 8);        // post s=8
    rec_gemm_kernel<<<g8k,  256>>>(W2, 512, state, out, 1, 4);        // post s=4
    rec_gemm_kernel<<<g16k, 256>>>(weight, 1024, state, out, 1, 2);   // post s=2

    (void)in_sizes; (void)n_in; (void)out_size;
}

// round 15
// speedup vs baseline: 1.3564x; 1.0946x over previous
#include <cuda_runtime.h>
#include <cuda_bf16.h>
#include <cstdint>

typedef unsigned long long u64;

// Problem dims
#define TT 2048
#define BB 16
#define II 512
#define HH 512
#define BH (BB*HH)   // 8192
#define RR (TT/32)   // 64 scan rounds (32-step blocking)

#define CLUSTER 8    // CTAs per cluster = 1 batch per cluster, 64 cols per CTA

// Scratch: W^2..W^32, row-major [512][512]. Static __device__ (legal).
__device__ float g_W2[HH * HH];
__device__ float g_W4[HH * HH];
__device__ float g_W8[HH * HH];
__device__ float g_W16[HH * HH];
__device__ float g_W32[HH * HH];

static __device__ __forceinline__ uint32_t smem_u32(const void* p) {
    uint32_t a;
    asm("{ .reg .u64 t; cvta.to.shared.u64 t, %1; cvt.u32.u64 %0, t; }"
        : "=r"(a) : "l"(p));
    return a;
}

#define FMA2(acc, a, b) \
    asm("fma.rn.f32x2 %0, %1, %2, %0;" : "+l"(acc) : "l"(a), "l"(b))
#define SPLAT2(dst, f) \
    asm("mov.b64 %0, {%1, %1};" : "=l"(dst) : "r"(__float_as_uint(f)))

// XOR swizzle: element (k, col) lives at physical column col ^ SWZ(k).
#define SWZ(kk) ((((kk) >> 2) & 7) << 2)

// ---------------------------------------------------------------------------
// Kernel 1: x_proj. 128x64 tile, 256 threads, 8x4 f32x2 microtile, swizzled.
// ---------------------------------------------------------------------------
__global__ __launch_bounds__(256)
void xproj_kernel(const float* __restrict__ A,      // inputs [M][512]
                  const float* __restrict__ W,      // weight [512][1024]
                  const float* __restrict__ bias,   // [512]
                  float* __restrict__ out)          // [M][512]
{
    __shared__ float As[32][132];
    __shared__ float Bs[32][68];

    const int tid = threadIdx.x;
    const int bm = blockIdx.x * 128;
    const int bn = blockIdx.y * 64;

    const int tx = tid & 15;
    const int ty = tid >> 4;

    u64 acc2[4][4];
#pragma unroll
    for (int r = 0; r < 4; r++)
#pragma unroll
        for (int c = 0; c < 4; c++) acc2[r][c] = 0ull;

#pragma unroll 1
    for (int kt = 0; kt < 16; kt++) {
        const int k0 = kt * 32;
#pragma unroll
        for (int j = 0; j < 4; j++) {
            int idx = tid + j * 256;
            int row = idx >> 3;
            int q   = idx & 7;
            int sw  = (q << 2);
            float4 v = *reinterpret_cast<const float4*>(&A[(size_t)(bm + row) * 512 + k0 + q * 4]);
            As[q * 4 + 0][row ^ sw] = v.x;
            As[q * 4 + 1][row ^ sw] = v.y;
            As[q * 4 + 2][row ^ sw] = v.z;
            As[q * 4 + 3][row ^ sw] = v.w;
        }
#pragma unroll
        for (int j = 0; j < 2; j++) {
            int idx = tid + j * 256;
            int row = idx >> 3;
            int q   = idx & 7;
            int sw  = (q << 2);
            float4 v = *reinterpret_cast<const float4*>(&W[(size_t)(bn + row) * 1024 + 512 + k0 + q * 4]);
            Bs[q * 4 + 0][row ^ sw] = v.x;
            Bs[q * 4 + 1][row ^ sw] = v.y;
            Bs[q * 4 + 2][row ^ sw] = v.z;
            Bs[q * 4 + 3][row ^ sw] = v.w;
        }
        __syncthreads();

#pragma unroll
        for (int k = 0; k < 32; k++) {
            const int s4 = SWZ(k);
            ulonglong2 a01 = *reinterpret_cast<const ulonglong2*>(&As[k][(ty * 8) ^ s4]);
            ulonglong2 a23 = *reinterpret_cast<const ulonglong2*>(&As[k][(ty * 8 + 4) ^ s4]);
            float4 b = *reinterpret_cast<const float4*>(&Bs[k][(tx * 4) ^ s4]);
            u64 bs[4];
            SPLAT2(bs[0], b.x); SPLAT2(bs[1], b.y);
            SPLAT2(bs[2], b.z); SPLAT2(bs[3], b.w);
            u64 apair[4] = {a01.x, a01.y, a23.x, a23.y};
#pragma unroll
            for (int r = 0; r < 4; r++)
#pragma unroll
                for (int c = 0; c < 4; c++)
                    FMA2(acc2[r][c], apair[r], bs[c]);
        }
        __syncthreads();
    }

#pragma unroll
    for (int r = 0; r < 4; r++) {
        size_t row0 = (size_t)(bm + ty * 8 + 2 * r) * 512 + bn + tx * 4;
#pragma unroll
        for (int c = 0; c < 4; c++) {
            uint32_t lo, hi;
            asm("mov.b64 {%0, %1}, %2;" : "=r"(lo), "=r"(hi) : "l"(acc2[r][c]));
            float bv = bias[bn + tx * 4 + c];
            out[row0 + c]       = __uint_as_float(lo) + bv;
            out[row0 + 512 + c] = __uint_as_float(hi) + bv;
        }
    }
}

// ---------------------------------------------------------------------------
// Kernel 1b: matrix squaring: dst = src @ src (rows stride sstride).
// ---------------------------------------------------------------------------
__global__ __launch_bounds__(256)
void mat_sq_kernel(const float* __restrict__ src, int sstride,
                   float* __restrict__ dst)
{
    __shared__ float As[32][68];   // [j][i]
    __shared__ float Bs[32][68];   // [j][k]

    const int tid = threadIdx.x;
    const int i0 = blockIdx.x * 64;
    const int k0g = blockIdx.y * 64;

    const int tx = tid & 15;
    const int ty = tid >> 4;

    float acc[4][4];
#pragma unroll
    for (int a = 0; a < 4; a++)
#pragma unroll
        for (int b = 0; b < 4; b++) acc[a][b] = 0.f;

#pragma unroll 1
    for (int jt = 0; jt < 16; jt++) {
        const int j0 = jt * 32;
#pragma unroll
        for (int l = 0; l < 2; l++) {
            int idx = tid + l * 256;
            int row = idx >> 3;
            int q   = idx & 7;
            float4 v = *reinterpret_cast<const float4*>(
                src + (size_t)(i0 + row) * sstride + j0 + q * 4);
            As[q * 4 + 0][row] = v.x;
            As[q * 4 + 1][row] = v.y;
            As[q * 4 + 2][row] = v.z;
            As[q * 4 + 3][row] = v.w;
        }
#pragma unroll
        for (int l = 0; l < 2; l++) {
            int idx = tid + l * 256;
            int jr  = idx >> 4;
            int q   = idx & 15;
            float4 v = *reinterpret_cast<const float4*>(
                src + (size_t)(j0 + jr) * sstride + k0g + q * 4);
            Bs[jr][q * 4 + 0] = v.x;
            Bs[jr][q * 4 + 1] = v.y;
            Bs[jr][q * 4 + 2] = v.z;
            Bs[jr][q * 4 + 3] = v.w;
        }
        __syncthreads();

#pragma unroll
        for (int j = 0; j < 32; j++) {
            float a[4], b[4];
#pragma unroll
            for (int x = 0; x < 4; x++) a[x] = As[j][ty * 4 + x];
#pragma unroll
            for (int x = 0; x < 4; x++) b[x] = Bs[j][tx * 4 + x];
#pragma unroll
            for (int x = 0; x < 4; x++)
#pragma unroll
                for (int y = 0; y < 4; y++)
                    acc[x][y] = fmaf(a[x], b[y], acc[x][y]);
        }
        __syncthreads();
    }

#pragma unroll
    for (int x = 0; x < 4; x++)
#pragma unroll
        for (int y = 0; y < 4; y++)
            dst[(size_t)(i0 + ty * 4 + x) * 512 + k0g + tx * 4 + y] = acc[x][y];
}

// ---------------------------------------------------------------------------
// Kernel 2: recurrent-side parallel GEMMs, swizzled 128x64 tile.
// Row m -> (rr = m>>4, bb = m&15). Level s in {2,4,8,16,32}:
//  pre  (mode 0): A slot = s*rr + s/2-1 ; D slot = s*rr + s-1
//  post (mode 1): A = (rr==0 ? state : slot s*rr-1) ; D slot = s*rr + s/2-1
// ---------------------------------------------------------------------------
__global__ __launch_bounds__(256)
void rec_gemm_kernel(const float* __restrict__ Wp, int wstride,
                     const float* __restrict__ state,  // [16][512]
                     float* __restrict__ out,
                     int mode, int s)
{
    __shared__ float As[32][132];
    __shared__ float Bs[32][68];

    const int tid = threadIdx.x;
    const int bm = blockIdx.x * 128;
    const int bn = blockIdx.y * 64;

    const int tx = tid & 15;
    const int ty = tid >> 4;

    u64 acc2[4][4];
#pragma unroll
    for (int r = 0; r < 4; r++)
#pragma unroll
        for (int c = 0; c < 4; c++) acc2[r][c] = 0ull;

#pragma unroll 1
    for (int kt = 0; kt < 16; kt++) {
        const int k0 = kt * 32;
#pragma unroll
        for (int j = 0; j < 4; j++) {
            int idx = tid + j * 256;
            int row = idx >> 3;
            int q   = idx & 7;
            int sw  = (q << 2);
            int m   = bm + row;
            int rr  = m >> 4;
            int bb  = m & 15;
            const float* arow;
            if (mode == 0) {
                arow = out + (size_t)(s * rr + s / 2 - 1) * BH + (size_t)bb * 512;
            } else {
                arow = (rr == 0) ? (state + (size_t)bb * 512)
                                 : (out + (size_t)(s * rr - 1) * BH + (size_t)bb * 512);
            }
            float4 v = *reinterpret_cast<const float4*>(arow + k0 + q * 4);
            As[q * 4 + 0][row ^ sw] = v.x;
            As[q * 4 + 1][row ^ sw] = v.y;
            As[q * 4 + 2][row ^ sw] = v.z;
            As[q * 4 + 3][row ^ sw] = v.w;
        }
#pragma unroll
        for (int j = 0; j < 2; j++) {
            int idx = tid + j * 256;
            int row = idx >> 3;
            int q   = idx & 7;
            int sw  = (q << 2);
            float4 v = *reinterpret_cast<const float4*>(
                Wp + (size_t)(bn + row) * wstride + k0 + q * 4);
            Bs[q * 4 + 0][row ^ sw] = v.x;
            Bs[q * 4 + 1][row ^ sw] = v.y;
            Bs[q * 4 + 2][row ^ sw] = v.z;
            Bs[q * 4 + 3][row ^ sw] = v.w;
        }
        __syncthreads();

#pragma unroll
        for (int k = 0; k < 32; k++) {
            const int s4 = SWZ(k);
            ulonglong2 a01 = *reinterpret_cast<const ulonglong2*>(&As[k][(ty * 8) ^ s4]);
            ulonglong2 a23 = *reinterpret_cast<const ulonglong2*>(&As[k][(ty * 8 + 4) ^ s4]);
            float4 b = *reinterpret_cast<const float4*>(&Bs[k][(tx * 4) ^ s4]);
            u64 bs[4];
            SPLAT2(bs[0], b.x); SPLAT2(bs[1], b.y);
            SPLAT2(bs[2], b.z); SPLAT2(bs[3], b.w);
            u64 apair[4] = {a01.x, a01.y, a23.x, a23.y};
#pragma unroll
            for (int r = 0; r < 4; r++)
#pragma unroll
                for (int c = 0; c < 4; c++)
                    FMA2(acc2[r][c], apair[r], bs[c]);
        }
        __syncthreads();
    }

    // epilogue: C = acc + D, in place
#pragma unroll
    for (int r = 0; r < 4; r++) {
#pragma unroll
        for (int par = 0; par < 2; par++) {
            int m  = bm + ty * 8 + 2 * r + par;
            int rr = m >> 4;
            int bb = m & 15;
            size_t slot = (mode == 0) ? (size_t)(s * rr + s - 1)
                                      : (size_t)(s * rr + s / 2 - 1);
            float* crow = out + slot * BH + (size_t)bb * 512 + bn + tx * 4;
#pragma unroll
            for (int c = 0; c < 4; c++) {
                uint32_t lo, hi;
                asm("mov.b64 {%0, %1}, %2;" : "=r"(lo), "=r"(hi) : "l"(acc2[r][c]));
                float v = par ? __uint_as_float(hi) : __uint_as_float(lo);
                crow[c] = v + crow[c];
            }
        }
    }
}

// ---------------------------------------------------------------------------
// Kernel 3: cluster scan — proven protocol, 64 rounds with W32:
//   h_{32t+31} = W32 @ h_{32t-1} + c5_t ; c5_t in out[32t+31] (overwritten).
// ---------------------------------------------------------------------------
__global__ void __cluster_dims__(CLUSTER, 1, 1) __launch_bounds__(512, 1)
scan_kernel(const float* __restrict__ state,   // [16][512]
            float* __restrict__ out)           // [T][16][512] + last [16][512]
{
    __shared__ float hsh[2][512];              // double-buffered h
    __shared__ float red[8][65];               // k-split partials
    __shared__ __align__(8) u64 mbar[2];       // full[buf] barriers

    const int tid  = threadIdx.x;
    const int col  = tid & 63;
    const int ks   = tid >> 6;                 // k in [ks*64, ks*64+64)
    const int rank = blockIdx.x & (CLUSTER - 1);
    const int b    = blockIdx.x / CLUSTER;     // batch
    const int c0   = rank * 64;
    const int gcol = c0 + col;

    // ---- W32 slice into registers (f32x2-packed over k) ----
    u64 wreg[32];
    {
        const u64* wp = reinterpret_cast<const u64*>(
            g_W32 + (size_t)gcol * 512 + ks * 64);
#pragma unroll
        for (int j = 0; j < 32; j += 2) {
            ulonglong2 v = *reinterpret_cast<const ulonglong2*>(wp + j);
            wreg[j]     = v.x;
            wreg[j + 1] = v.y;
        }
    }

    // ---- init: h_{-1} = state, barriers, cluster-wide visibility ----
    hsh[0][tid] = state[(size_t)b * 512 + tid];
    const uint32_t bar0 = smem_u32(&mbar[0]);
    const uint32_t bar1 = smem_u32(&mbar[1]);
    if (tid == 0) {
        asm volatile("mbarrier.init.shared.b64 [%0], 1;" :: "r"(bar0) : "memory");
        asm volatile("mbarrier.init.shared.b64 [%0], 1;" :: "r"(bar1) : "memory");
    }
    __syncthreads();
    asm volatile("barrier.cluster.arrive.aligned;" ::: "memory");
    asm volatile("barrier.cluster.wait.aligned;" ::: "memory");

    // ---- prefetch c5_0 (slot 31) ----
    float xp = 0.f;
    if (tid < 64)
        xp = __ldcg(out + (size_t)31 * BH + (size_t)b * HH + c0 + tid);

    const uint32_t laddr_h0 = smem_u32(&hsh[0][gcol]);
    const uint32_t laddr_h1 = smem_u32(&hsh[1][gcol]);

#pragma unroll 1
    for (int t = 0; t < RR; t++) {
        const int rb = t & 1;
        const uint32_t barw = rb ? bar1 : bar0;

        // ---- 1. wait for h from all 8 CTAs (2048 tx bytes) ----
        if (t > 0) {
            if (tid == 0)
                asm volatile("mbarrier.arrive.expect_tx.shared.b64 _, [%0], 2048;"
                             :: "r"(barw) : "memory");
            const uint32_t parity = ((unsigned)(t - 1) >> 1) & 1u;
            uint32_t done;
            asm volatile(
                "{\n\t.reg .pred p;\n\t"
                "mbarrier.try_wait.parity.acquire.cta.shared::cta.b64 p, [%1], %2;\n\t"
                "selp.b32 %0, 1, 0, p;\n\t}"
                : "=r"(done) : "r"(barw), "r"(parity) : "memory");
            while (!done) {
                asm volatile(
                    "{\n\t.reg .pred p;\n\t"
                    "mbarrier.try_wait.parity.acquire.cta.shared::cta.b64 p, [%1], %2, 0x989680;\n\t"
                    "selp.b32 %0, 1, 0, p;\n\t}"
                    : "=r"(done) : "r"(barw), "r"(parity) : "memory");
            }
        }

        // ---- 2. compute: packed f32x2 dot over this thread's 64 k's ----
        u64 accp = 0ull;
        const u64* hp = reinterpret_cast<const u64*>(&hsh[rb][ks * 64]);
#pragma unroll
        for (int j = 0; j < 32; j += 2) {
            ulonglong2 h2 = *reinterpret_cast<const ulonglong2*>(hp + j);
            FMA2(accp, wreg[j],     h2.x);
            FMA2(accp, wreg[j + 1], h2.y);
        }
        {
            uint32_t lo, hi;
            asm("mov.b64 {%0, %1}, %2;" : "=r"(lo), "=r"(hi) : "l"(accp));
            red[ks][col] = __uint_as_float(lo) + __uint_as_float(hi);
        }
        __syncthreads();

        // ---- 3. finalize (tid<64): reduce, publish via st.async, store out ----
        if (tid < 64) {
            float s = 0.f;
#pragma unroll
            for (int r = 0; r < 8; r++) s += red[r][tid];
            const float hn = s + xp;

            if (t + 1 < RR) {
                const uint32_t ldst = rb ? laddr_h0 : laddr_h1;
                const uint32_t lbar = rb ? bar0 : bar1;
#pragma unroll
                for (int r = 0; r < CLUSTER; r++) {
                    uint32_t raddr, rbar;
                    asm volatile("mapa.shared::cluster.u32 %0, %1, %2;"
                                 : "=r"(raddr) : "r"(ldst), "r"(r));
                    asm volatile("mapa.shared::cluster.u32 %0, %1, %2;"
                                 : "=r"(rbar) : "r"(lbar), "r"(r));
                    asm volatile(
                        "st.async.weak.shared::cluster.mbarrier::complete_tx::bytes.f32 [%0], %1, [%2];"
                        :: "r"(raddr), "f"(hn), "r"(rbar) : "memory");
                }
            }

            // out[32t+31] = h_{32t+31}
            const size_t off = (size_t)(32 * t + 31) * BH + (size_t)b * HH + c0 + tid;
            __stcg(out + off, hn);
            if (t == RR - 1)
                __stcg(out + (size_t)TT * BH + (size_t)b * HH + c0 + tid, hn);
            // prefetch c5_{t+1} from out[32t+63]
            if (t + 1 < RR)
                xp = __ldcg(out + (size_t)(32 * t + 63) * BH + (size_t)b * HH + c0 + tid);
        }
    }

    // ---- drain ----
    asm volatile("barrier.cluster.arrive.aligned;" ::: "memory");
    asm volatile("barrier.cluster.wait.aligned;" ::: "memory");
}

// ---------------------------------------------------------------------------
// Launch. Graph topology:
//   branch A (default stream): xproj -> pre(2) -> [join] -> pre(4..32) ->
//                              scan -> post(32..2)
//   branch B (forked stream):  W2 -> W4 -> W8 -> W16 -> W32
// Fork/join via disable-timing events (no device memory). Stream/events are
// intentionally leaked: kernel_launch runs only ~3 times (correctness +
// capture); replays execute the captured graph, not this function.
// ---------------------------------------------------------------------------
extern "C" void kernel_launch(void* const* d_in, const int* in_sizes, int n_in,
                              void* d_out, int out_size) {
    const float* inputs = (const float*)d_in[0];  // [T][B][I]
    const float* state  = (const float*)d_in[1];  // [B][H]
    const float* weight = (const float*)d_in[2];  // [H][I+H]
    const float* bias   = (const float*)d_in[3];  // [H]
    float* out = (float*)d_out;                   // [T][B][H] outputs, then [B][H] last

    float *W2, *W4, *W8, *W16, *W32;
    cudaGetSymbolAddress((void**)&W2,  g_W2);
    cudaGetSymbolAddress((void**)&W4,  g_W4);
    cudaGetSymbolAddress((void**)&W8,  g_W8);
    cudaGetSymbolAddress((void**)&W16, g_W16);
    cudaGetSymbolAddress((void**)&W32, g_W32);

    cudaStream_t s2;
    cudaStreamCreateWithFlags(&s2, cudaStreamNonBlocking);
    cudaEvent_t e1, e2;
    cudaEventCreateWithFlags(&e1, cudaEventDisableTiming);
    cudaEventCreateWithFlags(&e2, cudaEventDisableTiming);

    dim3 gw(8, 8);     // 512/64 x 512/64

    // ---- fork: W-power chain on branch B ----
    cudaEventRecord(e1, 0);
    cudaStreamWaitEvent(s2, e1, 0);
    mat_sq_kernel<<<gw, 256, 0, s2>>>(weight, 1024, W2);   // W2  = Whh^2
    mat_sq_kernel<<<gw, 256, 0, s2>>>(W2,  512, W4);       // W4  = W2^2
    mat_sq_kernel<<<gw, 256, 0, s2>>>(W4,  512, W8);       // W8  = W4^2
    mat_sq_kernel<<<gw, 256, 0, s2>>>(W8,  512, W16);      // W16 = W8^2
    mat_sq_kernel<<<gw, 256, 0, s2>>>(W16, 512, W32);      // W32 = W16^2
    cudaEventRecord(e2, s2);

    // ---- branch A: xproj + pre s=2 (need only weight/inputs) ----
    dim3 g1(256, 8);   // M=32768 / 128, N=512 / 64
    xproj_kernel<<<g1, 256>>>(inputs, weight, bias, out);

    dim3 g16k(128, 8); // M=16384 / 128
    dim3 g8k(64, 8);   // M=8192 / 128
    dim3 g4k(32, 8);   // M=4096 / 128
    dim3 g2k(16, 8);   // M=2048 / 128
    dim3 g1k(8, 8);    // M=1024 / 128

    rec_gemm_kernel<<<g16k, 256>>>(weight, 1024, state, out, 0, 2);   // pre s=2

    // ---- join: everything below needs W-powers ----
    cudaStreamWaitEvent(0, e2, 0);

    rec_gemm_kernel<<<g8k,  256>>>(W2,  512, state, out, 0, 4);       // pre s=4
    rec_gemm_kernel<<<g4k,  256>>>(W4,  512, state, out, 0, 8);       // pre s=8
    rec_gemm_kernel<<<g2k,  256>>>(W8,  512, state, out, 0, 16);      // pre s=16
    rec_gemm_kernel<<<g1k,  256>>>(W16, 512, state, out, 0, 32);      // pre s=32

    scan_kernel<<<BB * CLUSTER, 512>>>(state, out);                   // 64 rounds, W32

    rec_gemm_kernel<<<g1k,  256>>>(W16, 512, state, out, 1, 32);      // post s=32
    rec_gemm_kernel<<<g2k,  256>>>(W8,  512, state, out, 1, 16);      // post s=16
    rec_gemm_kernel<<<g4k,  256>>>(W4,  512, state, out, 1, 8);       // post s=8
    rec_gemm_kernel<<<g8k,  256>>>(W2,  512, state, out, 1, 4);       // post s=4
    rec_gemm_kernel<<<g16k, 256>>>(weight, 1024, state, out, 1, 2);   // post s=2

    (void)in_sizes; (void)n_in; (void)out_size;
}